// round 3
// baseline (speedup 1.0000x reference)
#include <cuda_runtime.h>
#include <cstdint>

// ---------------------------------------------------------------------------
// SkipGram negative-sampling: bit-exact JAX threefry gumbel top-k + dot products
// V=100000, D=512, B=1024, C=20, NEG=64
// ---------------------------------------------------------------------------

#define VV   100000
#define DD   512
#define BB   1024
#define CC   20
#define NEG  64
#define CAP  2048
#define T0   (-5.5)        // prefilter threshold: mean survivors e^5.5 ~ 245/row

extern "C" __device__ float __nv_logf(float);

// -------- static scratch --------
__device__ float    d_logp[VV];
__device__ unsigned d_thresh[VV];
__device__ int      d_cnt[BB];
__device__ unsigned d_cand_bits[BB * CAP];
__device__ int      d_cand_v[BB * CAP];
__device__ int      d_negidx[BB * NEG];

// ---------------------------------------------------------------------------
// threefry2x32, key (0,42). Pipe-balanced rounds:
//  Style A: add(IMAD,fma) + SHF(alu) + LOP3(alu)           -> 1 fma / 2 alu
//  Style C: add(IMAD,fma) + IMAD.WIDE(fma) + 3-in LOP3(alu) -> 2 fma / 1 alu
// rot(x,r) == (hi | lo) of (u64)x * (1u<<r), exact for 1<=r<=31.
// Multipliers arrive as opaque kernel args so cicc cannot fold them to shifts.
// ---------------------------------------------------------------------------
#define R_A(r) { x0 = x0 * one + x1;                                   \
                 x1 = __funnelshift_l(x1, x1, (r)) ^ x0; }
#define R_C(m) { x0 = x0 * one + x1;                                   \
                 unsigned long long w = (unsigned long long)x1 * (m);  \
                 x1 = (((unsigned)(w >> 32)) | ((unsigned)w)) ^ x0; }

__device__ __forceinline__ unsigned tf_bits(unsigned ctr, unsigned one,
                                            uint4 M) {
    const unsigned ks1 = 42u, ks2 = 0x1BD11BF0u;   // 0x1BD11BDA ^ 42
    unsigned x0 = 0u;
    unsigned x1 = ctr + ks1;
    R_A(13) R_C(M.x) R_A(26) R_C(M.y)          // M.x=1<<15, M.y=1<<6
    x0 += ks1; x1 += ks2 + 1u;
    R_A(17) R_C(M.z) R_A(16) R_C(M.w)          // M.z=1<<29, M.w=1<<24
    x0 += ks2; x1 += 2u;
    R_A(13) R_C(M.x) R_A(26) R_C(M.y)
    x1 += ks1 + 3u;
    R_A(17) R_C(M.z) R_A(16) R_C(M.w)
    x0 += ks1; x1 += ks2 + 4u;
    R_A(13) R_C(M.x) R_A(26) R_C(M.y)
    x0 += ks2; x1 += 5u;
    return x0 ^ x1;
}

// ---------------------------------------------------------------------------
// k0: per-word logp (exact f32) + conservative integer prefilter threshold
// (computed in double, margin 0.02 in score space). Zeroes cnt.
// ---------------------------------------------------------------------------
__global__ __launch_bounds__(256) void k0_tables(const float* __restrict__ p) {
    int v = blockIdx.x * 256 + threadIdx.x;
    if (v < BB) d_cnt[v] = 0;
    if (v >= VV) return;
    float pf = p[v];
    d_logp[v] = __nv_logf(pf);
    double lp = log((double)pf);
    double E = exp(lp - (T0 - 0.02));
    double ucrit = exp(-E);
    long long m = (long long)(floor(ucrit * 8388608.0)) - 2;
    if (m < 0) m = 0;
    if (m > 8388607) m = 8388607;
    d_thresh[v] = ((unsigned)m) << 9;
}

// ---------------------------------------------------------------------------
// k1: hot loop. 8 consecutive v per thread, one threefry + one unsigned
// compare each. Warp-aggregated push of survivors.
// ---------------------------------------------------------------------------
__global__ __launch_bounds__(256) void k1_filter(unsigned one, uint4 M) {
    const int b  = blockIdx.y;
    const int tg = blockIdx.x * 256 + threadIdx.x;
    const int v0 = tg * 8;
    const bool valid = (v0 < VV);          // VV % 8 == 0

    uint4 thA = make_uint4(~0u, ~0u, ~0u, ~0u);
    uint4 thB = thA;
    if (valid) {
        thA = *(const uint4*)&d_thresh[v0];
        thB = *(const uint4*)&d_thresh[v0 + 4];
    }
    unsigned th[8] = {thA.x, thA.y, thA.z, thA.w, thB.x, thB.y, thB.z, thB.w};

    unsigned base = (unsigned)b * (unsigned)VV + (unsigned)v0;

    unsigned bits[8]; bool kp[8];
    int nk = 0;
#pragma unroll
    for (int j = 0; j < 8; j++) {
        bits[j] = valid ? tf_bits(base + (unsigned)j, one, M) : 0u;
        kp[j]   = valid && (bits[j] >= th[j]);
        nk += (int)kp[j];
    }

    const unsigned fm = 0xFFFFFFFFu;
    const int lane = threadIdx.x & 31;
    int inc = nk;
#pragma unroll
    for (int d2 = 1; d2 < 32; d2 <<= 1) {
        int t = __shfl_up_sync(fm, inc, d2);
        if (lane >= d2) inc += t;
    }
    int excl  = inc - nk;
    int total = __shfl_sync(fm, inc, 31);
    int wbase = 0;
    if (lane == 31 && total > 0) wbase = atomicAdd(&d_cnt[b], total);
    wbase = __shfl_sync(fm, wbase, 31);

    int slot = wbase + excl;
#pragma unroll
    for (int j = 0; j < 8; j++) {
        if (kp[j] && slot < CAP) {
            d_cand_bits[b * CAP + slot] = bits[j];
            d_cand_v[b * CAP + slot]    = v0 + j;
            slot++;
        }
    }
}

// ---------------------------------------------------------------------------
// k2: exact rescoring (reference f32 arithmetic) + bitonic top-64.
// key = ordered(score)<<32 | (~v): ascending sort; read from end gives
// score desc, index asc (XLA tie-break).
// ---------------------------------------------------------------------------
__global__ __launch_bounds__(256) void k2_select() {
    __shared__ unsigned long long key[CAP];
    const int b = blockIdx.x;
    int n = d_cnt[b];
    if (n > CAP) n = CAP;

    for (int s = threadIdx.x; s < CAP; s += 256) {
        unsigned long long kk = 0ull;
        if (s < n) {
            unsigned bits = d_cand_bits[b * CAP + s];
            int v = d_cand_v[b * CAP + s];
            unsigned m = bits >> 9;
            float f  = __fadd_rn(__uint_as_float(m | 0x3f800000u), -1.0f);
            float u  = __fadd_rn(f, 1.17549435e-38f);
            float e  = -__nv_logf(u);
            float g  = -__nv_logf(e);
            float sc = __fadd_rn(d_logp[v], g);
            unsigned sb = __float_as_uint(sc);
            sb = (sb & 0x80000000u) ? ~sb : (sb | 0x80000000u);
            kk = ((unsigned long long)sb << 32)
               | (unsigned long long)(0xFFFFFFFFu - (unsigned)v);
        }
        key[s] = kk;
    }
    __syncthreads();

    int sz = 64;
    while (sz < n) sz <<= 1;

    for (int kk2 = 2; kk2 <= sz; kk2 <<= 1) {
        for (int j = kk2 >> 1; j > 0; j >>= 1) {
            for (int i = threadIdx.x; i < sz; i += 256) {
                int l = i ^ j;
                if (l > i) {
                    unsigned long long a = key[i], c = key[l];
                    bool up = ((i & kk2) == 0);
                    if ((a > c) == up) { key[i] = c; key[l] = a; }
                }
            }
            __syncthreads();
        }
    }

    if (threadIdx.x < NEG) {
        unsigned long long kk = key[sz - 1 - threadIdx.x];
        unsigned v = 0xFFFFFFFFu - (unsigned)(kk & 0xFFFFFFFFull);
        if (v >= VV) v = 0;
        d_negidx[b * NEG + threadIdx.x] = (int)v;
    }
}

// ---------------------------------------------------------------------------
// k3: gathers + dots. grid (B, 2); each warp processes TWO output rows per
// iteration with 8 independent float4 loads in flight (doubles MLP vs R2).
// ---------------------------------------------------------------------------
__device__ __forceinline__ const float4* k3_row(int b, int j,
                                                const int* __restrict__ context_ids,
                                                const float* __restrict__ Wc,
                                                const float* __restrict__ Wx) {
    if (j < CC) return (const float4*)(Wc + (size_t)context_ids[b * CC + j] * DD);
    return (const float4*)(Wx + (size_t)d_negidx[b * NEG + (j - CC)] * DD);
}

__global__ __launch_bounds__(256) void k3_dots(const int* __restrict__ center_ids,
                                               const int* __restrict__ context_ids,
                                               const float* __restrict__ Wc,
                                               const float* __restrict__ Wx,
                                               float* __restrict__ out) {
    __shared__ float ctr[DD];
    const int b = blockIdx.x;
    const size_t crow = (size_t)center_ids[b] * DD;
    for (int i = threadIdx.x; i < DD; i += 256) ctr[i] = Wc[crow + i];
    __syncthreads();

    const int warp = threadIdx.x >> 5;
    const int lane = threadIdx.x & 31;
    const float4* ctr4 = (const float4*)ctr;

    const int j0 = blockIdx.y * 42;
    const int j1 = (blockIdx.y == 0) ? 42 : (CC + NEG);

    for (int j = j0 + warp; j < j1; j += 16) {
        const int ja = j;
        const int jb = j + 8;
        const bool hb = (jb < j1);
        const float4* rA = k3_row(b, ja, context_ids, Wc, Wx);
        const float4* rB = hb ? k3_row(b, jb, context_ids, Wc, Wx) : rA;

        float accA = 0.0f, accB = 0.0f;
#pragma unroll
        for (int t = 0; t < 4; t++) {
            float4 a = rA[lane + 32 * t];
            float4 bb = rB[lane + 32 * t];
            float4 c = ctr4[lane + 32 * t];
            accA += a.x * c.x + a.y * c.y + a.z * c.z + a.w * c.w;
            accB += bb.x * c.x + bb.y * c.y + bb.z * c.z + bb.w * c.w;
        }
#pragma unroll
        for (int d2 = 16; d2 > 0; d2 >>= 1) {
            accA += __shfl_down_sync(0xFFFFFFFFu, accA, d2);
            accB += __shfl_down_sync(0xFFFFFFFFu, accB, d2);
        }
        if (lane == 0) {
            if (ja < CC) out[b * CC + ja] = accA;
            else         out[BB * CC + b * NEG + (ja - CC)] = accA;
            if (hb) {
                if (jb < CC) out[b * CC + jb] = accB;
                else         out[BB * CC + b * NEG + (jb - CC)] = accB;
            }
        }
    }
}

// ---------------------------------------------------------------------------
extern "C" void kernel_launch(void* const* d_in, const int* in_sizes, int n_in,
                              void* d_out, int out_size) {
    const int*   center_ids  = (const int*)d_in[0];
    const int*   context_ids = (const int*)d_in[1];
    const float* W_center    = (const float*)d_in[2];
    const float* W_context   = (const float*)d_in[3];
    const float* sample_prob = (const float*)d_in[4];
    float* out = (float*)d_out;

    k0_tables<<<(VV + 255) / 256, 256>>>(sample_prob);

    dim3 g1((VV / 8 + 255) / 256, BB);   // 49 x 1024 CTAs
    uint4 M = make_uint4(1u << 15, 1u << 6, 1u << 29, 1u << 24);
    k1_filter<<<g1, 256>>>(1u, M);

    k2_select<<<BB, 256>>>();

    dim3 g3(BB, 2);
    k3_dots<<<g3, 256>>>(center_ids, context_ids, W_center, W_context, out);
}

// round 4
// speedup vs baseline: 1.1134x; 1.1134x over previous
#include <cuda_runtime.h>
#include <cstdint>

// ---------------------------------------------------------------------------
// SkipGram negative-sampling: bit-exact JAX threefry gumbel top-k + dot products
// V=100000, D=512, B=1024, C=20, NEG=64
// ---------------------------------------------------------------------------

#define VV   100000
#define DD   512
#define BB   1024
#define CC   20
#define NEG  64
#define CAP  2048
#define T0   (-5.5)        // prefilter threshold: mean survivors e^5.5 ~ 245/row
#define HASH_CTAS 49       // ceil(VV/8/256)

extern "C" __device__ float __nv_logf(float);

// -------- static scratch --------
__device__ float    d_logp[VV];
__device__ unsigned d_thresh[VV];
__device__ int      d_cnt[BB];
__device__ unsigned d_cand_bits[BB * CAP];
__device__ int      d_cand_v[BB * CAP];
__device__ int      d_negidx[BB * NEG];

// ---------------------------------------------------------------------------
// threefry2x32, key (0,42). Round add forced to IMAD (fma pipe) via opaque
// `one`; alu pipe carries SHF+LOP3 only. (R2 structure — best measured.)
// ---------------------------------------------------------------------------
#define TFR(r) { x0 = x0 * one + x1; x1 = __funnelshift_l(x1, x1, (r)) ^ x0; }

__device__ __forceinline__ unsigned tf_bits(unsigned ctr, unsigned one) {
    const unsigned ks1 = 42u, ks2 = 0x1BD11BF0u;   // 0x1BD11BDA ^ 42
    unsigned x0 = 0u;
    unsigned x1 = ctr + ks1;
    TFR(13) TFR(15) TFR(26) TFR(6)
    x0 += ks1; x1 += ks2 + 1u;
    TFR(17) TFR(29) TFR(16) TFR(24)
    x0 += ks2; x1 += 2u;
    TFR(13) TFR(15) TFR(26) TFR(6)
    x1 += ks1 + 3u;
    TFR(17) TFR(29) TFR(16) TFR(24)
    x0 += ks1; x1 += ks2 + 4u;
    TFR(13) TFR(15) TFR(26) TFR(6)
    x0 += ks2; x1 += 5u;
    return x0 ^ x1;
}

// ---------------------------------------------------------------------------
// k0: per-word logp (exact f32) + conservative integer prefilter threshold
// (computed in double, margin 0.02 in score space). Zeroes cnt.
// ---------------------------------------------------------------------------
__global__ __launch_bounds__(256) void k0_tables(const float* __restrict__ p) {
    int v = blockIdx.x * 256 + threadIdx.x;
    if (v < BB) d_cnt[v] = 0;
    if (v >= VV) return;
    float pf = p[v];
    d_logp[v] = __nv_logf(pf);
    double lp = log((double)pf);
    double E = exp(lp - (T0 - 0.02));
    double ucrit = exp(-E);
    long long m = (long long)(floor(ucrit * 8388608.0)) - 2;
    if (m < 0) m = 0;
    if (m > 8388607) m = 8388607;
    d_thresh[v] = ((unsigned)m) << 9;
}

// ---------------------------------------------------------------------------
// k1 (fused): grid (HASH_CTAS+3, B).
//  blockIdx.x <  HASH_CTAS : hash path — 8 v per thread, threefry + compare,
//                            warp-aggregated push of survivors.
//  blockIdx.x >= HASH_CTAS : positive-dot path — 8 warps compute up to 8 of
//                            the 20 W_center[context].center dots. These
//                            memory-bound CTAs overlap with the alu-bound
//                            hash CTAs on the same SMs.
// ---------------------------------------------------------------------------
__global__ __launch_bounds__(256) void k1_fused(unsigned one,
                                                const int* __restrict__ center_ids,
                                                const int* __restrict__ context_ids,
                                                const float* __restrict__ Wc,
                                                float* __restrict__ out) {
    const int b = blockIdx.y;

    if (blockIdx.x >= HASH_CTAS) {
        // ---- positive dots ----
        __shared__ float ctr[DD];
        const int k = blockIdx.x - HASH_CTAS;           // 0..2
        const size_t crow = (size_t)center_ids[b] * DD;
        for (int i = threadIdx.x; i < DD; i += 256) ctr[i] = Wc[crow + i];
        __syncthreads();
        const int warp = threadIdx.x >> 5;
        const int lane = threadIdx.x & 31;
        const int j = k * 8 + warp;
        if (j < CC) {
            const float4* row4 = (const float4*)(Wc + (size_t)context_ids[b * CC + j] * DD);
            const float4* ctr4 = (const float4*)ctr;
            float acc = 0.0f;
#pragma unroll
            for (int t = 0; t < 4; t++) {
                float4 r = row4[lane + 32 * t];
                float4 c = ctr4[lane + 32 * t];
                acc += r.x * c.x + r.y * c.y + r.z * c.z + r.w * c.w;
            }
#pragma unroll
            for (int d2 = 16; d2 > 0; d2 >>= 1)
                acc += __shfl_down_sync(0xFFFFFFFFu, acc, d2);
            if (lane == 0) out[b * CC + j] = acc;
        }
        return;
    }

    // ---- hash path ----
    const int tg = blockIdx.x * 256 + threadIdx.x;
    const int v0 = tg * 8;
    const bool valid = (v0 < VV);          // VV % 8 == 0

    uint4 thA = make_uint4(~0u, ~0u, ~0u, ~0u);
    uint4 thB = thA;
    if (valid) {
        thA = *(const uint4*)&d_thresh[v0];
        thB = *(const uint4*)&d_thresh[v0 + 4];
    }
    unsigned th[8] = {thA.x, thA.y, thA.z, thA.w, thB.x, thB.y, thB.z, thB.w};

    unsigned base = (unsigned)b * (unsigned)VV + (unsigned)v0;

    unsigned bits[8]; bool kp[8];
    int nk = 0;
#pragma unroll
    for (int j = 0; j < 8; j++) {
        bits[j] = valid ? tf_bits(base + (unsigned)j, one) : 0u;
        kp[j]   = valid && (bits[j] >= th[j]);
        nk += (int)kp[j];
    }

    const unsigned fm = 0xFFFFFFFFu;
    const int lane = threadIdx.x & 31;
    int inc = nk;
#pragma unroll
    for (int d2 = 1; d2 < 32; d2 <<= 1) {
        int t = __shfl_up_sync(fm, inc, d2);
        if (lane >= d2) inc += t;
    }
    int excl  = inc - nk;
    int total = __shfl_sync(fm, inc, 31);
    int wbase = 0;
    if (lane == 31 && total > 0) wbase = atomicAdd(&d_cnt[b], total);
    wbase = __shfl_sync(fm, wbase, 31);

    int slot = wbase + excl;
#pragma unroll
    for (int j = 0; j < 8; j++) {
        if (kp[j] && slot < CAP) {
            d_cand_bits[b * CAP + slot] = bits[j];
            d_cand_v[b * CAP + slot]    = v0 + j;
            slot++;
        }
    }
}

// ---------------------------------------------------------------------------
// k2: exact rescoring (reference f32 arithmetic) + bitonic top-64.
// key = ordered(score)<<32 | (~v): ascending sort; read from end gives
// score desc, index asc (XLA tie-break).
// ---------------------------------------------------------------------------
__global__ __launch_bounds__(256) void k2_select() {
    __shared__ unsigned long long key[CAP];
    const int b = blockIdx.x;
    int n = d_cnt[b];
    if (n > CAP) n = CAP;

    for (int s = threadIdx.x; s < CAP; s += 256) {
        unsigned long long kk = 0ull;
        if (s < n) {
            unsigned bits = d_cand_bits[b * CAP + s];
            int v = d_cand_v[b * CAP + s];
            unsigned m = bits >> 9;
            float f  = __fadd_rn(__uint_as_float(m | 0x3f800000u), -1.0f);
            float u  = __fadd_rn(f, 1.17549435e-38f);
            float e  = -__nv_logf(u);
            float g  = -__nv_logf(e);
            float sc = __fadd_rn(d_logp[v], g);
            unsigned sb = __float_as_uint(sc);
            sb = (sb & 0x80000000u) ? ~sb : (sb | 0x80000000u);
            kk = ((unsigned long long)sb << 32)
               | (unsigned long long)(0xFFFFFFFFu - (unsigned)v);
        }
        key[s] = kk;
    }
    __syncthreads();

    int sz = 64;
    while (sz < n) sz <<= 1;

    for (int kk2 = 2; kk2 <= sz; kk2 <<= 1) {
        for (int j = kk2 >> 1; j > 0; j >>= 1) {
            for (int i = threadIdx.x; i < sz; i += 256) {
                int l = i ^ j;
                if (l > i) {
                    unsigned long long a = key[i], c = key[l];
                    bool up = ((i & kk2) == 0);
                    if ((a > c) == up) { key[i] = c; key[l] = a; }
                }
            }
            __syncthreads();
        }
    }

    if (threadIdx.x < NEG) {
        unsigned long long kk = key[sz - 1 - threadIdx.x];
        unsigned v = 0xFFFFFFFFu - (unsigned)(kk & 0xFFFFFFFFull);
        if (v >= VV) v = 0;
        d_negidx[b * NEG + threadIdx.x] = (int)v;
    }
}

// ---------------------------------------------------------------------------
// k3: negatives only. grid (B, 16), 128 threads = 4 warps, ONE output row per
// warp, all 4 float4 loads front-batched — max warp-level MLP, no loop.
// ---------------------------------------------------------------------------
__global__ __launch_bounds__(128) void k3_neg(const int* __restrict__ center_ids,
                                              const float* __restrict__ Wc,
                                              const float* __restrict__ Wx,
                                              float* __restrict__ out) {
    __shared__ float ctr[DD];
    const int b = blockIdx.x;
    const size_t crow = (size_t)center_ids[b] * DD;
    for (int i = threadIdx.x; i < DD; i += 128) ctr[i] = Wc[crow + i];
    __syncthreads();

    const int warp = threadIdx.x >> 5;
    const int lane = threadIdx.x & 31;
    const int jn = blockIdx.y * 4 + warp;            // 0..63

    const float4* row4 = (const float4*)(Wx + (size_t)d_negidx[b * NEG + jn] * DD);
    const float4* ctr4 = (const float4*)ctr;
    float acc = 0.0f;
#pragma unroll
    for (int t = 0; t < 4; t++) {
        float4 r = row4[lane + 32 * t];
        float4 c = ctr4[lane + 32 * t];
        acc += r.x * c.x + r.y * c.y + r.z * c.z + r.w * c.w;
    }
#pragma unroll
    for (int d2 = 16; d2 > 0; d2 >>= 1)
        acc += __shfl_down_sync(0xFFFFFFFFu, acc, d2);
    if (lane == 0) out[BB * CC + b * NEG + jn] = acc;
}

// ---------------------------------------------------------------------------
extern "C" void kernel_launch(void* const* d_in, const int* in_sizes, int n_in,
                              void* d_out, int out_size) {
    const int*   center_ids  = (const int*)d_in[0];
    const int*   context_ids = (const int*)d_in[1];
    const float* W_center    = (const float*)d_in[2];
    const float* W_context   = (const float*)d_in[3];
    const float* sample_prob = (const float*)d_in[4];
    float* out = (float*)d_out;

    k0_tables<<<(VV + 255) / 256, 256>>>(sample_prob);

    dim3 g1(HASH_CTAS + 3, BB);   // 49 hash CTAs + 3 positive-dot CTAs per row
    k1_fused<<<g1, 256>>>(1u, center_ids, context_ids, W_center, out);

    k2_select<<<BB, 256>>>();

    dim3 g3(BB, 16);
    k3_neg<<<g3, 128>>>(center_ids, W_center, W_context, out);
}

// round 5
// speedup vs baseline: 1.2050x; 1.0822x over previous
#include <cuda_runtime.h>
#include <cstdint>

// ---------------------------------------------------------------------------
// SkipGram negative-sampling: bit-exact JAX threefry gumbel top-k + dot products
// V=100000, D=512, B=1024, C=20, NEG=64
// ---------------------------------------------------------------------------

#define VV   100000
#define DD   512
#define BB   1024
#define CC   20
#define NEG  64
#define CAP  1024
#define T0   (-5.5)        // prefilter: mean survivors e^5.5 ~ 245/row (CAP=50sig)
#define HASH_CTAS 25       // 25*256*16 = 102400 >= VV

extern "C" __device__ float __nv_logf(float);

// -------- static scratch --------
__device__ float    d_logp[VV];
__device__ unsigned d_thresh[VV];
__device__ int      d_cnt[BB];
__device__ int      d_cand_v[BB * CAP];
__device__ int      d_negidx[BB * NEG];

// ---------------------------------------------------------------------------
// threefry2x32, key (0,42). Round add forced to IMAD (fma pipe) via opaque
// `one`; alu pipe carries SHF+LOP3 only.
// ---------------------------------------------------------------------------
#define TFR(r) { x0 = x0 * one + x1; x1 = __funnelshift_l(x1, x1, (r)) ^ x0; }

__device__ __forceinline__ unsigned tf_bits(unsigned ctr, unsigned one) {
    const unsigned ks1 = 42u, ks2 = 0x1BD11BF0u;   // 0x1BD11BDA ^ 42
    unsigned x0 = 0u;
    unsigned x1 = ctr + ks1;
    TFR(13) TFR(15) TFR(26) TFR(6)
    x0 += ks1; x1 += ks2 + 1u;
    TFR(17) TFR(29) TFR(16) TFR(24)
    x0 += ks2; x1 += 2u;
    TFR(13) TFR(15) TFR(26) TFR(6)
    x1 += ks1 + 3u;
    TFR(17) TFR(29) TFR(16) TFR(24)
    x0 += ks1; x1 += ks2 + 4u;
    TFR(13) TFR(15) TFR(26) TFR(6)
    x0 += ks2; x1 += 5u;
    return x0 ^ x1;
}

// ---------------------------------------------------------------------------
// k0: per-word logp (exact f32) + conservative integer prefilter threshold
// (double precision, margin 0.02 in score space). Zeroes cnt.
// ---------------------------------------------------------------------------
__global__ __launch_bounds__(256) void k0_tables(const float* __restrict__ p) {
    int v = blockIdx.x * 256 + threadIdx.x;
    if (v < BB) d_cnt[v] = 0;
    if (v >= VV) return;
    float pf = p[v];
    d_logp[v] = __nv_logf(pf);
    double lp = log((double)pf);
    double E = exp(lp - (T0 - 0.02));
    double ucrit = exp(-E);
    long long m = (long long)(floor(ucrit * 8388608.0)) - 2;
    if (m < 0) m = 0;
    if (m > 8388607) m = 8388607;
    d_thresh[v] = ((unsigned)m) << 9;
}

// ---------------------------------------------------------------------------
// k1 (fused): grid (HASH_CTAS+3, B).
//  x <  HASH_CTAS : hash path — 16 v per thread, compute-and-discard threefry,
//                   per-survivor atomicAdd (~0.6/warp; cheaper than a scan).
//  x >= HASH_CTAS : positive-dot CTAs (memory-bound, overlap with alu-bound
//                   hash CTAs on the same SMs).
// ---------------------------------------------------------------------------
__global__ __launch_bounds__(256) void k1_fused(unsigned one,
                                                const int* __restrict__ center_ids,
                                                const int* __restrict__ context_ids,
                                                const float* __restrict__ Wc,
                                                float* __restrict__ out) {
    const int b = blockIdx.y;

    if (blockIdx.x >= HASH_CTAS) {
        // ---- positive dots ----
        __shared__ float ctr[DD];
        const int k = blockIdx.x - HASH_CTAS;           // 0..2
        const size_t crow = (size_t)center_ids[b] * DD;
        for (int i = threadIdx.x; i < DD; i += 256) ctr[i] = Wc[crow + i];
        __syncthreads();
        const int warp = threadIdx.x >> 5;
        const int lane = threadIdx.x & 31;
        const int j = k * 8 + warp;
        if (j < CC) {
            const float4* row4 = (const float4*)(Wc + (size_t)context_ids[b * CC + j] * DD);
            const float4* ctr4 = (const float4*)ctr;
            float acc = 0.0f;
#pragma unroll
            for (int t = 0; t < 4; t++) {
                float4 r = row4[lane + 32 * t];
                float4 c = ctr4[lane + 32 * t];
                acc += r.x * c.x + r.y * c.y + r.z * c.z + r.w * c.w;
            }
#pragma unroll
            for (int d2 = 16; d2 > 0; d2 >>= 1)
                acc += __shfl_down_sync(0xFFFFFFFFu, acc, d2);
            if (lane == 0) out[b * CC + j] = acc;
        }
        return;
    }

    // ---- hash path: 16 consecutive v per thread ----
    const int tg = blockIdx.x * 256 + threadIdx.x;
    const int v0 = tg * 16;
    if (v0 >= VV) return;                   // VV % 16 == 0: per-thread uniform

    unsigned th[16];
#pragma unroll
    for (int q = 0; q < 4; q++) {
        uint4 t = *(const uint4*)&d_thresh[v0 + 4 * q];
        th[4 * q + 0] = t.x; th[4 * q + 1] = t.y;
        th[4 * q + 2] = t.z; th[4 * q + 3] = t.w;
    }

    const unsigned base = (unsigned)b * (unsigned)VV + (unsigned)v0;

#pragma unroll
    for (int j = 0; j < 16; j++) {
        unsigned bits = tf_bits(base + (unsigned)j, one);
        if (bits >= th[j]) {
            int pos = atomicAdd(&d_cnt[b], 1);
            if (pos < CAP) d_cand_v[b * CAP + pos] = v0 + j;
        }
    }
}

// ---------------------------------------------------------------------------
// k2: recompute hash for each candidate, exact rescoring (reference f32
// arithmetic), bitonic top-64. key = ordered(score)<<32 | (~v): ascending
// sort; read from end = score desc, index asc (XLA tie-break).
// ---------------------------------------------------------------------------
__global__ __launch_bounds__(256) void k2_select(unsigned one) {
    __shared__ unsigned long long key[CAP];
    const int b = blockIdx.x;
    int n = d_cnt[b];
    if (n > CAP) n = CAP;

    for (int s = threadIdx.x; s < CAP; s += 256) {
        unsigned long long kk = 0ull;
        if (s < n) {
            int v = d_cand_v[b * CAP + s];
            unsigned bits = tf_bits((unsigned)b * (unsigned)VV + (unsigned)v, one);
            unsigned m = bits >> 9;
            float f  = __fadd_rn(__uint_as_float(m | 0x3f800000u), -1.0f);
            float u  = __fadd_rn(f, 1.17549435e-38f);
            float e  = -__nv_logf(u);
            float g  = -__nv_logf(e);
            float sc = __fadd_rn(d_logp[v], g);
            unsigned sb = __float_as_uint(sc);
            sb = (sb & 0x80000000u) ? ~sb : (sb | 0x80000000u);
            kk = ((unsigned long long)sb << 32)
               | (unsigned long long)(0xFFFFFFFFu - (unsigned)v);
        }
        key[s] = kk;
    }
    __syncthreads();

    int sz = 64;
    while (sz < n) sz <<= 1;

    for (int kk2 = 2; kk2 <= sz; kk2 <<= 1) {
        for (int j = kk2 >> 1; j > 0; j >>= 1) {
            for (int i = threadIdx.x; i < sz; i += 256) {
                int l = i ^ j;
                if (l > i) {
                    unsigned long long a = key[i], c = key[l];
                    bool up = ((i & kk2) == 0);
                    if ((a > c) == up) { key[i] = c; key[l] = a; }
                }
            }
            __syncthreads();
        }
    }

    if (threadIdx.x < NEG) {
        unsigned long long kk = key[sz - 1 - threadIdx.x];
        unsigned v = 0xFFFFFFFFu - (unsigned)(kk & 0xFFFFFFFFull);
        if (v >= VV) v = 0;
        d_negidx[b * NEG + threadIdx.x] = (int)v;
    }
}

// ---------------------------------------------------------------------------
// k3: negatives only. grid (B, 8), 256 threads = 8 warps, ONE row per warp,
// 4 front-batched float4 loads (max MLP), half the center-load redundancy.
// ---------------------------------------------------------------------------
__global__ __launch_bounds__(256) void k3_neg(const int* __restrict__ center_ids,
                                              const float* __restrict__ Wc,
                                              const float* __restrict__ Wx,
                                              float* __restrict__ out) {
    __shared__ float ctr[DD];
    const int b = blockIdx.x;
    const size_t crow = (size_t)center_ids[b] * DD;
    for (int i = threadIdx.x; i < DD; i += 256) ctr[i] = Wc[crow + i];
    __syncthreads();

    const int warp = threadIdx.x >> 5;
    const int lane = threadIdx.x & 31;
    const int jn = blockIdx.y * 8 + warp;            // 0..63

    const float4* row4 = (const float4*)(Wx + (size_t)d_negidx[b * NEG + jn] * DD);
    const float4* ctr4 = (const float4*)ctr;
    float acc = 0.0f;
#pragma unroll
    for (int t = 0; t < 4; t++) {
        float4 r = row4[lane + 32 * t];
        float4 c = ctr4[lane + 32 * t];
        acc += r.x * c.x + r.y * c.y + r.z * c.z + r.w * c.w;
    }
#pragma unroll
    for (int d2 = 16; d2 > 0; d2 >>= 1)
        acc += __shfl_down_sync(0xFFFFFFFFu, acc, d2);
    if (lane == 0) out[BB * CC + b * NEG + jn] = acc;
}

// ---------------------------------------------------------------------------
extern "C" void kernel_launch(void* const* d_in, const int* in_sizes, int n_in,
                              void* d_out, int out_size) {
    const int*   center_ids  = (const int*)d_in[0];
    const int*   context_ids = (const int*)d_in[1];
    const float* W_center    = (const float*)d_in[2];
    const float* W_context   = (const float*)d_in[3];
    const float* sample_prob = (const float*)d_in[4];
    float* out = (float*)d_out;

    k0_tables<<<(VV + 255) / 256, 256>>>(sample_prob);

    dim3 g1(HASH_CTAS + 3, BB);   // 25 hash CTAs + 3 positive-dot CTAs per row
    k1_fused<<<g1, 256>>>(1u, center_ids, context_ids, W_center, out);

    k2_select<<<BB, 256>>>(1u);

    dim3 g3(BB, 8);
    k3_neg<<<g3, 256>>>(center_ids, W_center, W_context, out);
}

// round 6
// speedup vs baseline: 1.2731x; 1.0566x over previous
#include <cuda_runtime.h>
#include <cstdint>

// ---------------------------------------------------------------------------
// SkipGram negative-sampling: bit-exact JAX threefry gumbel top-k + dot products
// V=100000, D=512, B=1024, C=20, NEG=64
// ---------------------------------------------------------------------------

#define VV   100000
#define DD   512
#define BB   1024
#define CC   20
#define NEG  64
#define CAP  512
#define T0   (-5.5)        // prefilter: mean survivors ~e^5.55 ~ 257/row
#define HASH_CTAS 25       // 25*256*16 = 102400 >= VV

extern "C" __device__ float __nv_logf(float);

// -------- static scratch --------
__device__ float    d_logp[VV];
__device__ unsigned d_thresh[VV];
__device__ int      d_cnt[BB];
__device__ int      d_cand_v[BB * CAP];

// ---------------------------------------------------------------------------
// threefry2x32, key (0,42). Round add forced to IMAD (fma pipe) via opaque
// `one`; alu pipe carries SHF+LOP3 only.
// ---------------------------------------------------------------------------
#define TFR(r) { x0 = x0 * one + x1; x1 = __funnelshift_l(x1, x1, (r)) ^ x0; }

__device__ __forceinline__ unsigned tf_bits(unsigned ctr, unsigned one) {
    const unsigned ks1 = 42u, ks2 = 0x1BD11BF0u;   // 0x1BD11BDA ^ 42
    unsigned x0 = 0u;
    unsigned x1 = ctr + ks1;
    TFR(13) TFR(15) TFR(26) TFR(6)
    x0 += ks1; x1 += ks2 + 1u;
    TFR(17) TFR(29) TFR(16) TFR(24)
    x0 += ks2; x1 += 2u;
    TFR(13) TFR(15) TFR(26) TFR(6)
    x1 += ks1 + 3u;
    TFR(17) TFR(29) TFR(16) TFR(24)
    x0 += ks1; x1 += ks2 + 4u;
    TFR(13) TFR(15) TFR(26) TFR(6)
    x0 += ks2; x1 += 5u;
    return x0 ^ x1;
}

// ---------------------------------------------------------------------------
// k0: per-word logp (exact f32, used by rescoring) + conservative integer
// prefilter threshold — float/MUFU path, margin 0.05 in score space plus an
// 8-ulp guard, both strictly enlarging the candidate set. Zeroes cnt.
// ---------------------------------------------------------------------------
__global__ __launch_bounds__(256) void k0_tables(const float* __restrict__ p) {
    int v = blockIdx.x * 256 + threadIdx.x;
    if (v < BB) d_cnt[v] = 0;
    if (v >= VV) return;
    float pf = p[v];
    float lp = __nv_logf(pf);
    d_logp[v] = lp;
    float E = __expf(lp - (float)(T0 - 0.05));
    float ucrit = __expf(-E);
    int m = (int)floorf(ucrit * 8388608.0f) - 8;
    if (m < 0) m = 0;
    if (m > 8388607) m = 8388607;
    d_thresh[v] = ((unsigned)m) << 9;
}

// ---------------------------------------------------------------------------
// k1 (fused): grid (HASH_CTAS+3, B).
//  x <  HASH_CTAS : hash path — 16 v per thread, compute-and-discard threefry,
//                   per-survivor atomicAdd (~0.6/warp).
//  x >= HASH_CTAS : positive-dot CTAs (memory-bound, overlap with alu-bound
//                   hash CTAs on the same SMs).
// ---------------------------------------------------------------------------
__global__ __launch_bounds__(256) void k1_fused(unsigned one,
                                                const int* __restrict__ center_ids,
                                                const int* __restrict__ context_ids,
                                                const float* __restrict__ Wc,
                                                float* __restrict__ out) {
    const int b = blockIdx.y;

    if (blockIdx.x >= HASH_CTAS) {
        // ---- positive dots ----
        __shared__ float ctr[DD];
        const int k = blockIdx.x - HASH_CTAS;           // 0..2
        const size_t crow = (size_t)center_ids[b] * DD;
        for (int i = threadIdx.x; i < DD; i += 256) ctr[i] = Wc[crow + i];
        __syncthreads();
        const int warp = threadIdx.x >> 5;
        const int lane = threadIdx.x & 31;
        const int j = k * 8 + warp;
        if (j < CC) {
            const float4* row4 = (const float4*)(Wc + (size_t)context_ids[b * CC + j] * DD);
            const float4* ctr4 = (const float4*)ctr;
            float acc = 0.0f;
#pragma unroll
            for (int t = 0; t < 4; t++) {
                float4 r = row4[lane + 32 * t];
                float4 c = ctr4[lane + 32 * t];
                acc += r.x * c.x + r.y * c.y + r.z * c.z + r.w * c.w;
            }
#pragma unroll
            for (int d2 = 16; d2 > 0; d2 >>= 1)
                acc += __shfl_down_sync(0xFFFFFFFFu, acc, d2);
            if (lane == 0) out[b * CC + j] = acc;
        }
        return;
    }

    // ---- hash path: 16 consecutive v per thread ----
    const int tg = blockIdx.x * 256 + threadIdx.x;
    const int v0 = tg * 16;
    if (v0 >= VV) return;                   // VV % 16 == 0: per-thread uniform

    unsigned th[16];
#pragma unroll
    for (int q = 0; q < 4; q++) {
        uint4 t = *(const uint4*)&d_thresh[v0 + 4 * q];
        th[4 * q + 0] = t.x; th[4 * q + 1] = t.y;
        th[4 * q + 2] = t.z; th[4 * q + 3] = t.w;
    }

    const unsigned base = (unsigned)b * (unsigned)VV + (unsigned)v0;

#pragma unroll
    for (int j = 0; j < 16; j++) {
        unsigned bits = tf_bits(base + (unsigned)j, one);
        if (bits >= th[j]) {
            int pos = atomicAdd(&d_cnt[b], 1);
            if (pos < CAP) d_cand_v[b * CAP + pos] = v0 + j;
        }
    }
}

// ---------------------------------------------------------------------------
// k2 (fused select + negative dots): one CTA per b.
//  1. recompute hash per candidate, exact reference-f32 rescoring
//  2. bitonic top-64 (key = ordered(score)<<32 | ~v: score desc, index asc)
//  3. 8 warps stream the 64 negative rows of W_context and dot with center.
// Sorting of some CTAs overlaps the DRAM gather phase of others.
// ---------------------------------------------------------------------------
__global__ __launch_bounds__(256) void k2_fused(unsigned one,
                                                const int* __restrict__ center_ids,
                                                const float* __restrict__ Wc,
                                                const float* __restrict__ Wx,
                                                float* __restrict__ out) {
    __shared__ unsigned long long key[CAP];
    __shared__ float ctr[DD];
    __shared__ int   negs[NEG];
    const int b = blockIdx.x;
    int n = d_cnt[b];
    if (n > CAP) n = CAP;

    // center row -> smem (overlaps with candidate rescoring)
    const size_t crow = (size_t)center_ids[b] * DD;
    for (int i = threadIdx.x; i < DD; i += 256) ctr[i] = Wc[crow + i];

    for (int s = threadIdx.x; s < CAP; s += 256) {
        unsigned long long kk = 0ull;
        if (s < n) {
            int v = d_cand_v[b * CAP + s];
            unsigned bits = tf_bits((unsigned)b * (unsigned)VV + (unsigned)v, one);
            unsigned m = bits >> 9;
            float f  = __fadd_rn(__uint_as_float(m | 0x3f800000u), -1.0f);
            float u  = __fadd_rn(f, 1.17549435e-38f);
            float e  = -__nv_logf(u);
            float g  = -__nv_logf(e);
            float sc = __fadd_rn(d_logp[v], g);
            unsigned sb = __float_as_uint(sc);
            sb = (sb & 0x80000000u) ? ~sb : (sb | 0x80000000u);
            kk = ((unsigned long long)sb << 32)
               | (unsigned long long)(0xFFFFFFFFu - (unsigned)v);
        }
        key[s] = kk;
    }
    __syncthreads();

    int sz = 64;
    while (sz < n) sz <<= 1;               // <= CAP

    for (int kk2 = 2; kk2 <= sz; kk2 <<= 1) {
        for (int j = kk2 >> 1; j > 0; j >>= 1) {
            for (int i = threadIdx.x; i < sz; i += 256) {
                int l = i ^ j;
                if (l > i) {
                    unsigned long long a = key[i], c = key[l];
                    bool up = ((i & kk2) == 0);
                    if ((a > c) == up) { key[i] = c; key[l] = a; }
                }
            }
            __syncthreads();
        }
    }

    if (threadIdx.x < NEG) {
        unsigned long long kk = key[sz - 1 - threadIdx.x];
        unsigned v = 0xFFFFFFFFu - (unsigned)(kk & 0xFFFFFFFFull);
        if (v >= VV) v = 0;
        negs[threadIdx.x] = (int)v;
    }
    __syncthreads();

    // ---- negative dots: 8 warps x 8 rows each ----
    const int warp = threadIdx.x >> 5;
    const int lane = threadIdx.x & 31;
    const float4* ctr4 = (const float4*)ctr;
#pragma unroll
    for (int it = 0; it < 8; it++) {
        const int jn = it * 8 + warp;      // 0..63
        const float4* row4 = (const float4*)(Wx + (size_t)negs[jn] * DD);
        float acc = 0.0f;
#pragma unroll
        for (int t = 0; t < 4; t++) {
            float4 r = row4[lane + 32 * t];
            float4 c = ctr4[lane + 32 * t];
            acc += r.x * c.x + r.y * c.y + r.z * c.z + r.w * c.w;
        }
#pragma unroll
        for (int d2 = 16; d2 > 0; d2 >>= 1)
            acc += __shfl_down_sync(0xFFFFFFFFu, acc, d2);
        if (lane == 0) out[BB * CC + b * NEG + jn] = acc;
    }
}

// ---------------------------------------------------------------------------
extern "C" void kernel_launch(void* const* d_in, const int* in_sizes, int n_in,
                              void* d_out, int out_size) {
    const int*   center_ids  = (const int*)d_in[0];
    const int*   context_ids = (const int*)d_in[1];
    const float* W_center    = (const float*)d_in[2];
    const float* W_context   = (const float*)d_in[3];
    const float* sample_prob = (const float*)d_in[4];
    float* out = (float*)d_out;

    k0_tables<<<(VV + 255) / 256, 256>>>(sample_prob);

    dim3 g1(HASH_CTAS + 3, BB);   // 25 hash CTAs + 3 positive-dot CTAs per row
    k1_fused<<<g1, 256>>>(1u, center_ids, context_ids, W_center, out);

    k2_fused<<<BB, 256>>>(1u, center_ids, W_center, W_context, out);
}